// round 15
// baseline (speedup 1.0000x reference)
#include <cuda_runtime.h>
#include <cuda_bf16.h>
#include <math.h>
#include <stdint.h>

// ============================================================================
// ODE-RNN: B=128, F=512, I=128, H=512, O=1, NSTEP=5
//
// R15 vs R14 (21.25 ms; LDS-pipe bound: 1 LDS.128 per 2 fma2):
//  * register blocking: thread = 4 rows x 2 cols (warp = 2 half-warps x
//    16 lanes). Each h LDS.128 feeds 4 fma2 -> h-LDS halved.
//  * W1 in registers (2 cols x 64 k = 64 u64/thread, loaded once).
//  * W2/Whh in even/odd-split SMEM arrays: per k4 exactly 2 broadcast
//    LDS.128 for both columns.
//  * h tile in SMEM padded to row stride 516 -> the two half-warp
//    addresses land on disjoint banks (1 wavefront per h load).
//  * everything else (comm warp, flush-free red.release barrier, .cg
//    data path, dual 8-sample groups) carried from R14 unchanged.
// ============================================================================

#define BB     128
#define FF     512
#define IDIM   128
#define HH     512
#define NSTEPS 5
#define NGRP   16    // batch groups
#define BG     8     // samples per group
#define NC     16    // column CTAs per group
#define HC     32    // columns per CTA
#define NCW    8     // compute warps
#define NTHR   (32 * (NCW + 1))   // 288
#define KW     64    // k-slice width per compute warp
#define BARN   (NC * NCW)         // 128 arrivals per group per phase
#define HST    516   // padded h row stride (4x516 % 32 == 16: bank-disjoint halves)

// ---------------- device scratch (no cudaMalloc allowed) -------------------
__device__ float    g_xproj[(size_t)FF * BB * HH];  // 128 MiB
__device__ float    g_h[NGRP * BG * HH];
__device__ float    g_a[NGRP * BG * HH];
__device__ float    g_part[NC * BB];
__device__ unsigned g_ctr[NGRP * 32];

// ---------------- dynamic SMEM layout (float offsets) ----------------------
#define SM_HB0  0                       // 8 x 516
#define SM_HB1  (BG * HST)              // 4128
#define SM_W2E  (2 * BG * HST)          // 8256   (128 k4 x 16 li x 4)
#define SM_W2O  (SM_W2E + 8192)         // 16448
#define SM_WHE  (SM_W2O + 8192)         // 24640
#define SM_WHO  (SM_WHE + 8192)         // 32832
#define SM_RED  (SM_WHO + 8192)         // 41024  (64 x 34)
#define SM_SC   (SM_RED + 64 * 34)      // 43200
#define SM_TOT  ((SM_SC + 2 * BG) * 4)  // 172,864 bytes

// ---------------- packed f32x2 helpers -------------------------------------
__device__ __forceinline__ unsigned long long fma2(unsigned long long a,
                                                   unsigned long long b,
                                                   unsigned long long c) {
    unsigned long long d;
    asm("fma.rn.f32x2 %0, %1, %2, %3;" : "=l"(d) : "l"(a), "l"(b), "l"(c));
    return d;
}
__device__ __forceinline__ float upsum(unsigned long long v) {
    float lo, hi;
    asm("mov.b64 {%0, %1}, %2;" : "=f"(lo), "=f"(hi) : "l"(v));
    return lo + hi;
}

// ---------------- named barriers --------------------------------------------
#define BARX(id, cnt) asm volatile("bar.sync %0, %1;" :: "r"(id), "r"(cnt) : "memory")

// ---------------- flush-free arrival ----------------------------------------
__device__ __forceinline__ void arrive(unsigned* ctr, int lane) {
    __syncwarp();
    if (lane == 0)
        asm volatile("red.release.gpu.global.add.u32 [%0], 1;" :: "l"(ctr) : "memory");
}

// ---------------- comm-warp primitives --------------------------------------
__device__ __forceinline__ void comm_wait(unsigned* ctr, unsigned target, int cwl) {
    if (cwl == 0) {
        unsigned v;
        do {
            asm volatile("ld.relaxed.gpu.global.u32 %0, [%1];"
                         : "=r"(v) : "l"(ctr) : "memory");
        } while (v < target);
    }
    __syncwarp();
}
// stage 8x512 fp32 tile (global, contiguous) -> SMEM rows of stride HST
__device__ __forceinline__ void comm_stage(const float* src, float* dst, int cwl) {
    unsigned dbase = (unsigned)__cvta_generic_to_shared(dst);
#pragma unroll
    for (int i = 0; i < 32; ++i) {
        int cidx = i * 32 + cwl;          // 16B chunk id, 0..1023
        int r = cidx >> 7, o = cidx & 127;
        unsigned    ds = dbase + (unsigned)((r * HST + o * 4) * 4);
        const char* gs = (const char*)src + (size_t)cidx * 16;
        asm volatile("cp.async.cg.shared.global [%0], [%1], 16;"
                     :: "r"(ds), "l"(gs));
    }
    asm volatile("cp.async.commit_group;" ::: "memory");
    asm volatile("cp.async.wait_group 0;" ::: "memory");
}

// ---------------- GEMM cores: thread = 4 rows x 2 cols ----------------------
// acc[rr][cc] over this warp's k-slice [k0, k0+64)
__device__ __forceinline__ void gemmA(const unsigned long long w1r[2][KW / 2],
                                      const float* __restrict__ hb,
                                      int k0, int half,
                                      unsigned long long acc[4][2]) {
#pragma unroll
    for (int rr = 0; rr < 4; ++rr)
#pragma unroll
        for (int cc = 0; cc < 2; ++cc) acc[rr][cc] = 0ull;
#pragma unroll
    for (int k4 = 0; k4 < KW / 4; ++k4) {
        ulonglong2 hv[4];
#pragma unroll
        for (int rr = 0; rr < 4; ++rr)
            hv[rr] = *(const ulonglong2*)(hb + (half * 4 + rr) * HST + k0 + 4 * k4);
#pragma unroll
        for (int rr = 0; rr < 4; ++rr)
#pragma unroll
            for (int cc = 0; cc < 2; ++cc) {
                acc[rr][cc] = fma2(w1r[cc][2 * k4],     hv[rr].x, acc[rr][cc]);
                acc[rr][cc] = fma2(w1r[cc][2 * k4 + 1], hv[rr].y, acc[rr][cc]);
            }
    }
}

// weights from even/odd split SMEM (W2 or Whh)
__device__ __forceinline__ void gemmS(const float* __restrict__ we,
                                      const float* __restrict__ wo,
                                      const float* __restrict__ hb,
                                      int w, int li, int k0, int half,
                                      unsigned long long acc[4][2]) {
#pragma unroll
    for (int rr = 0; rr < 4; ++rr)
#pragma unroll
        for (int cc = 0; cc < 2; ++cc) acc[rr][cc] = 0ull;
#pragma unroll
    for (int k4 = 0; k4 < KW / 4; ++k4) {
        int k4g = w * 16 + k4;
        ulonglong2 wve = *(const ulonglong2*)(we + ((k4g * 16 + li) << 2));
        ulonglong2 wvo = *(const ulonglong2*)(wo + ((k4g * 16 + li) << 2));
        ulonglong2 hv[4];
#pragma unroll
        for (int rr = 0; rr < 4; ++rr)
            hv[rr] = *(const ulonglong2*)(hb + (half * 4 + rr) * HST + k0 + 4 * k4);
#pragma unroll
        for (int rr = 0; rr < 4; ++rr) {
            acc[rr][0] = fma2(wve.x, hv[rr].x, acc[rr][0]);
            acc[rr][0] = fma2(wve.y, hv[rr].y, acc[rr][0]);
            acc[rr][1] = fma2(wvo.x, hv[rr].x, acc[rr][1]);
            acc[rr][1] = fma2(wvo.y, hv[rr].y, acc[rr][1]);
        }
    }
}

// split-k reduction: after this, thread (w,l) owns (row w, col l)
__device__ __forceinline__ void reduceN(float* red, unsigned long long acc[4][2],
                                        int w, int l, int half, int li, float& s) {
#pragma unroll
    for (int rr = 0; rr < 4; ++rr) {
        int r = half * 4 + rr;
        float2 v = make_float2(upsum(acc[rr][0]), upsum(acc[rr][1]));
        *(float2*)(red + (w * 8 + r) * 34 + 2 * li) = v;
    }
    BARX(3, 256);
    s = 0.0f;
#pragma unroll
    for (int wp = 0; wp < NCW; ++wp)
        s += red[(wp * 8 + w) * 34 + l];
}

// ============================================================================
__global__ void pad_kernel() {
    if (threadIdx.x > 1024) g_ctr[0] = 1u;  // never true
}

__global__ void init_kernel() {
    int t = blockIdx.x * blockDim.x + threadIdx.x;
    if (t < NGRP * 32) g_ctr[t] = 0u;
    for (int i = t; i < NGRP * BG * HH; i += gridDim.x * blockDim.x)
        g_h[i] = 0.0f;
}

// ============================================================================
// xproj[f][b][h] = x[b,f,:] @ Wih^T + bih + bhh
// ============================================================================
__global__ void __launch_bounds__(256) xproj_kernel(const float* __restrict__ x,
                                                    const float* __restrict__ Wih,
                                                    const float* __restrict__ bih,
                                                    const float* __restrict__ bhh) {
    __shared__ float4 xs[16 * (IDIM / 4)];
    const int tid   = threadIdx.x;
    const int m0    = blockIdx.x * 16;
    const int j     = blockIdx.y * 128 + (tid & 127);
    const int rbase = (tid >> 7) * 8;

    const float4* xg = (const float4*)(x + (size_t)m0 * IDIM);
#pragma unroll
    for (int it = 0; it < 2; ++it) xs[tid + it * 256] = xg[tid + it * 256];
    __syncthreads();

    const float4* wr = (const float4*)(Wih + (size_t)j * IDIM);
    float acc[8];
#pragma unroll
    for (int r = 0; r < 8; ++r) acc[r] = 0.0f;

#pragma unroll 4
    for (int k = 0; k < IDIM / 4; ++k) {
        float4 wv = __ldg(wr + k);
#pragma unroll
        for (int r = 0; r < 8; ++r) {
            float4 xv = xs[(rbase + r) * (IDIM / 4) + k];
            acc[r] += wv.x * xv.x + wv.y * xv.y + wv.z * xv.z + wv.w * xv.w;
        }
    }
    const float bias = __ldg(bih + j) + __ldg(bhh + j);
#pragma unroll
    for (int r = 0; r < 8; ++r) {
        int mm = m0 + rbase + r;
        int b  = mm >> 9;
        int f  = mm & 511;
        g_xproj[((size_t)f * BB + b) * HH + j] = acc[r] + bias;
    }
}

// ============================================================================
// persistent recurrence: 128 CTAs = 8 group-pairs x 16 col-CTAs
//   warps 0-7: compute (k-slices).   warp 8: comm (spin+stage+release).
// ============================================================================
__global__ void __launch_bounds__(NTHR, 1)
odernn_persist(const float* __restrict__ tp,
               const float* __restrict__ W1, const float* __restrict__ b1,
               const float* __restrict__ W2, const float* __restrict__ b2,
               const float* __restrict__ Whh, const float* __restrict__ Wc) {
    extern __shared__ float smem[];
    float* hb0 = smem + SM_HB0;
    float* hb1 = smem + SM_HB1;
    float* w2e = smem + SM_W2E;
    float* w2o = smem + SM_W2O;
    float* whe = smem + SM_WHE;
    float* who = smem + SM_WHO;
    float* red = smem + SM_RED;
    float* scs = smem + SM_SC;

    const int tid  = threadIdx.x;
    const int m    = blockIdx.x >> 4;   // group pair 0..7
    const int c    = blockIdx.x & 15;   // column block
    const int w    = tid >> 5;          // warp id (8 = comm)
    const int l    = tid & 31;
    const int half = l >> 4;            // half-warp: row group AND weight parity
    const int li   = l & 15;
    const int g0   = 2 * m, g1 = 2 * m + 1;

    float*    hg0  = g_h + g0 * BG * HH;
    float*    hg1  = g_h + g1 * BG * HH;
    float*    ag0  = g_a + g0 * BG * HH;
    float*    ag1  = g_a + g1 * BG * HH;
    unsigned* ctr0 = &g_ctr[g0 * 32];
    unsigned* ctr1 = &g_ctr[g1 * 32];

    // ------------------- setup -------------------------------------------
    unsigned long long w1r[2][KW / 2];
    float b1j = 0.0f, b2j = 0.0f;
    int j = 0, k0 = 0;
    if (w < NCW) {
        j  = c * HC + l;     // output ownership column (post-reduce)
        k0 = w * KW;
        // W1 k-slice for this thread's 2 columns -> registers
#pragma unroll
        for (int cc = 0; cc < 2; ++cc) {
            int jc = c * HC + 2 * li + cc;
            const ulonglong2* p = (const ulonglong2*)(W1 + (size_t)jc * HH + k0);
#pragma unroll
            for (int i = 0; i < KW / 4; ++i) {
                ulonglong2 v = __ldg(p + i);
                w1r[cc][2 * i]     = v.x;
                w1r[cc][2 * i + 1] = v.y;
            }
        }
        // W2 / Whh -> even/odd split SMEM (parity = half)
#pragma unroll
        for (int i = 0; i < 16; ++i) {
            int k4g = w * 16 + i;
            int jc  = c * HC + 2 * li + half;
            float* d2 = (half ? w2o : w2e) + ((k4g * 16 + li) << 2);
            float* dh = (half ? who : whe) + ((k4g * 16 + li) << 2);
            *(float4*)d2 = *(const float4*)(W2  + (size_t)jc * HH + 4 * k4g);
            *(float4*)dh = *(const float4*)(Whh + (size_t)jc * HH + 4 * k4g);
        }
        b1j = __ldg(b1 + j);
        b2j = __ldg(b2 + j);
    }
    __syncthreads();

    if (w == NCW) {
        // =================== COMM WARP =====================================
        const int cwl = l;
        unsigned q = 0;
        for (int f = 0; f < FF; ++f) {
            for (int ph = 0; ph < 2 * NSTEPS + 1; ++ph) {
                const float* s0 = (ph & 1) ? ag0 : hg0;
                const float* s1 = (ph & 1) ? ag1 : hg1;
                if (ph == 2 * NSTEPS) { s0 = hg0; s1 = hg1; }

                comm_wait(ctr0, q * BARN, cwl);
                comm_stage(s0, hb0, cwl);
                if (ph == 0 && cwl < 2 * BG) {
                    int qq = cwl >> 3, r = cwl & 7;
                    int b = (2 * m + qq) * BG + r;
                    float d = (f == 0) ? 0.0f
                                       : (__ldcg(tp + b * FF + f) - __ldcg(tp + b * FF + f - 1));
                    scs[qq * BG + r] = d * (1.0f / NSTEPS);
                }
                BARX(1, NTHR);

                comm_wait(ctr1, q * BARN, cwl);
                comm_stage(s1, hb1, cwl);
                BARX(2, NTHR);
                ++q;
            }
        }
    } else {
        // =================== COMPUTE WARPS =================================
        float hown0 = 0.0f, hown1 = 0.0f;
        float fs0 = 0.0f, fs1 = 0.0f;
        unsigned long long acc[4][2];
        float sum;

        for (int f = 0; f < FF; ++f) {
            for (int s5 = 0; s5 < NSTEPS; ++s5) {
                // ---- phase A: a = relu(h @ W1^T + b1) ----
                BARX(1, NTHR);
                gemmA(w1r, hb0, k0, half, acc);
                reduceN(red, acc, w, l, half, li, sum);
                __stcg(ag0 + w * HH + j, fmaxf(sum + b1j, 0.0f));
                arrive(ctr0, l);
                BARX(2, NTHR);
                gemmA(w1r, hb1, k0, half, acc);
                reduceN(red, acc, w, l, half, li, sum);
                __stcg(ag1 + w * HH + j, fmaxf(sum + b1j, 0.0f));
                arrive(ctr1, l);

                // ---- phase B: h += (a @ W2^T + b2) * scale ----
                BARX(1, NTHR);
                gemmS(w2e, w2o, hb0, w, li, k0, half, acc);
                reduceN(red, acc, w, l, half, li, sum);
                hown0 += (sum + b2j) * scs[w];
                __stcg(hg0 + w * HH + j, hown0);
                arrive(ctr0, l);
                BARX(2, NTHR);
                gemmS(w2e, w2o, hb1, w, li, k0, half, acc);
                reduceN(red, acc, w, l, half, li, sum);
                hown1 += (sum + b2j) * scs[BG + w];
                __stcg(hg1 + w * HH + j, hown1);
                arrive(ctr1, l);
            }

            // ---- phase C: h = tanh(xproj + hp @ Whh^T) ----
            BARX(1, NTHR);
            {
                float xp0 = __ldcg(g_xproj + ((size_t)f * BB + g0 * BG + w) * HH + j);
                gemmS(whe, who, hb0, w, li, k0, half, acc);
                reduceN(red, acc, w, l, half, li, sum);
                hown0 = tanhf(sum + xp0);
                fs0 += hown0;
                __stcg(hg0 + w * HH + j, hown0);
                arrive(ctr0, l);
            }
            BARX(2, NTHR);
            {
                float xp1 = __ldcg(g_xproj + ((size_t)f * BB + g1 * BG + w) * HH + j);
                gemmS(whe, who, hb1, w, li, k0, half, acc);
                reduceN(red, acc, w, l, half, li, sum);
                hown1 = tanhf(sum + xp1);
                fs1 += hown1;
                __stcg(hg1 + w * HH + j, hown1);
                arrive(ctr1, l);
            }
        }

        // ---- classifier partials ----
        const float wcj = __ldg(Wc + j);
        float p0 = fs0 * wcj * (1.0f / FF);
        float p1 = fs1 * wcj * (1.0f / FF);
#pragma unroll
        for (int o = 16; o; o >>= 1) {
            p0 += __shfl_xor_sync(0xffffffffu, p0, o);
            p1 += __shfl_xor_sync(0xffffffffu, p1, o);
        }
        if (l == 0) {
            g_part[c * BB + g0 * BG + w] = p0;
            g_part[c * BB + g1 * BG + w] = p1;
        }
    }
}

// ============================================================================
__global__ void finalize_kernel(const float* __restrict__ bc, float* __restrict__ out) {
    int b = threadIdx.x;
    float s = __ldg(bc);
#pragma unroll
    for (int c = 0; c < NC; ++c) s += g_part[c * BB + b];
    out[b] = 1.0f / (1.0f + expf(-s));
}

// ============================================================================
extern "C" void kernel_launch(void* const* d_in, const int* in_sizes, int n_in,
                              void* d_out, int out_size) {
    const float* x   = (const float*)d_in[0];
    const float* tp  = (const float*)d_in[1];
    const float* W1  = (const float*)d_in[2];
    const float* b1  = (const float*)d_in[3];
    const float* W2  = (const float*)d_in[4];
    const float* b2  = (const float*)d_in[5];
    const float* Wih = (const float*)d_in[6];
    const float* Whh = (const float*)d_in[7];
    const float* bih = (const float*)d_in[8];
    const float* bhh = (const float*)d_in[9];
    const float* Wc  = (const float*)d_in[10];
    const float* bc  = (const float*)d_in[11];
    float* out = (float*)d_out;

    cudaFuncSetAttribute(odernn_persist,
                         cudaFuncAttributeMaxDynamicSharedMemorySize, SM_TOT);

    pad_kernel<<<1, 32>>>();   // keeps ncu capture window on odernn_persist

    init_kernel<<<64, 256>>>();

    dim3 gx(BB * FF / 16, HH / 128);
    xproj_kernel<<<gx, 256>>>(x, Wih, bih, bhh);

    odernn_persist<<<128, NTHR, SM_TOT>>>(tp, W1, b1, W2, b2, Whh, Wc);

    finalize_kernel<<<1, BB>>>(bc, out);

    (void)in_sizes; (void)n_in; (void)out_size;
}